// round 2
// baseline (speedup 1.0000x reference)
#include <cuda_runtime.h>
#include <math.h>

#define NTOK   16384
#define DM     1024
#define DF     4096
#define NE     8

// ---- routing scratch + intermediate activation scratch (allocation-free) ----
__device__ int   g_cnt[NE];
__device__ int   g_off[NE];
__device__ int   g_fill[NE];
__device__ int   g_list[NTOK];                       // token ids sorted by expert
__device__ float g_h[(size_t)NTOK * DF];             // 256 MB intermediate H

// ---------------------------------------------------------------- routing ----
// NOTE: expert_indices is int32 on device (JAX x64 disabled -> jnp.int64 is int32).
__global__ void k_route0() {
    if (threadIdx.x < NE) { g_cnt[threadIdx.x] = 0; g_fill[threadIdx.x] = 0; }
}

__global__ void k_route1(const int* __restrict__ idx) {
    int t = blockIdx.x * blockDim.x + threadIdx.x;
    if (t < NTOK) atomicAdd(&g_cnt[idx[t]], 1);
}

__global__ void k_route2() {
    if (threadIdx.x == 0) {
        int s = 0;
        for (int e = 0; e < NE; e++) { g_off[e] = s; s += g_cnt[e]; }
    }
}

__global__ void k_route3(const int* __restrict__ idx) {
    int t = blockIdx.x * blockDim.x + threadIdx.x;
    if (t < NTOK) {
        int e = idx[t];
        int p = atomicAdd(&g_fill[e], 1);
        g_list[g_off[e] + p] = t;
    }
}

// jax.nn.gelu default: approximate=True (tanh form)
__device__ __forceinline__ float gelu_tanh(float x) {
    float x3 = x * x * x;
    return 0.5f * x * (1.0f + tanhf(0.7978845608028654f * (x + 0.044715f * x3)));
}

// ---------------------------------------------------------------- GEMM 1 ----
// H[p, n] = gelu( X[list[p], :] @ W1[e][:, n] + b1[e][n] ),  p in [off[e], off[e]+cnt[e])
// BM=128, BN=128, BK=8, 256 threads, 8x8 per thread.
__global__ __launch_bounds__(256, 2) void k_gemm1(
    const float* __restrict__ X, const float* __restrict__ W1,
    const float* __restrict__ b1)
{
    int e   = blockIdx.z;
    int cnt = g_cnt[e];
    int m0  = blockIdx.x * 128;
    if (m0 >= cnt) return;
    int off = g_off[e];
    int n0  = blockIdx.y * 128;
    const float* B = W1 + (size_t)e * DM * DF;

    __shared__ float As[8][128];   // [k][m] (transposed)
    __shared__ float Bs[8][128];   // [k][n]

    int tid = threadIdx.x;
    int tx = tid & 15, ty = tid >> 4;

    // A tile load map: 128 rows x 8 k = 1024 elems, float4 per thread
    int am  = tid >> 1;            // row within tile
    int akq = (tid & 1) * 4;       // k quad
    int mg  = m0 + am;
    const float* arow = (mg < cnt) ? (X + (size_t)g_list[off + mg] * DM) : nullptr;

    // B tile load map: 8 k x 128 n, float4 per thread (fully coalesced)
    int bk = tid >> 5;
    int bn = (tid & 31) * 4;

    float acc[8][8];
    #pragma unroll
    for (int i = 0; i < 8; i++)
        #pragma unroll
        for (int j = 0; j < 8; j++) acc[i][j] = 0.f;

    for (int k0 = 0; k0 < DM; k0 += 8) {
        float4 av = make_float4(0.f, 0.f, 0.f, 0.f);
        if (arow) av = *(const float4*)(arow + k0 + akq);
        float4 bv = *(const float4*)(B + (size_t)(k0 + bk) * DF + n0 + bn);
        As[akq + 0][am] = av.x; As[akq + 1][am] = av.y;
        As[akq + 2][am] = av.z; As[akq + 3][am] = av.w;
        *(float4*)&Bs[bk][bn] = bv;
        __syncthreads();
        #pragma unroll
        for (int kk = 0; kk < 8; kk++) {
            float a[8], b[8];
            #pragma unroll
            for (int i = 0; i < 8; i++) a[i] = As[kk][ty * 8 + i];
            #pragma unroll
            for (int j = 0; j < 8; j++) b[j] = Bs[kk][tx * 8 + j];
            #pragma unroll
            for (int i = 0; i < 8; i++)
                #pragma unroll
                for (int j = 0; j < 8; j++)
                    acc[i][j] += a[i] * b[j];
        }
        __syncthreads();
    }

    // epilogue: + b1, gelu, store to H (vectorized)
    const float* bb = b1 + (size_t)e * DF + n0 + tx * 8;
    float4 b1lo = *(const float4*)(bb);
    float4 b1hi = *(const float4*)(bb + 4);
    #pragma unroll
    for (int i = 0; i < 8; i++) {
        int m = m0 + ty * 8 + i;
        if (m < cnt) {
            float* hrow = g_h + (size_t)(off + m) * DF + n0 + tx * 8;
            float4 v0, v1;
            v0.x = gelu_tanh(acc[i][0] + b1lo.x);
            v0.y = gelu_tanh(acc[i][1] + b1lo.y);
            v0.z = gelu_tanh(acc[i][2] + b1lo.z);
            v0.w = gelu_tanh(acc[i][3] + b1lo.w);
            v1.x = gelu_tanh(acc[i][4] + b1hi.x);
            v1.y = gelu_tanh(acc[i][5] + b1hi.y);
            v1.z = gelu_tanh(acc[i][6] + b1hi.z);
            v1.w = gelu_tanh(acc[i][7] + b1hi.w);
            *(float4*)(hrow)     = v0;
            *(float4*)(hrow + 4) = v1;
        }
    }
}

// ---------------------------------------------------------------- GEMM 2 ----
// out[list[p], n] = H[p, :] @ W2[e][:, n] + b2[e][n]
__global__ __launch_bounds__(256, 2) void k_gemm2(
    const float* __restrict__ W2, const float* __restrict__ b2,
    float* __restrict__ out)
{
    int e   = blockIdx.z;
    int cnt = g_cnt[e];
    int m0  = blockIdx.x * 128;
    if (m0 >= cnt) return;
    int off = g_off[e];
    int n0  = blockIdx.y * 128;
    const float* B = W2 + (size_t)e * DF * DM;

    __shared__ float As[8][128];
    __shared__ float Bs[8][128];

    int tid = threadIdx.x;
    int tx = tid & 15, ty = tid >> 4;

    int am  = tid >> 1;
    int akq = (tid & 1) * 4;
    int mg  = m0 + am;
    const float* arow = (mg < cnt) ? (g_h + (size_t)(off + mg) * DF) : nullptr;

    int bk = tid >> 5;
    int bn = (tid & 31) * 4;

    float acc[8][8];
    #pragma unroll
    for (int i = 0; i < 8; i++)
        #pragma unroll
        for (int j = 0; j < 8; j++) acc[i][j] = 0.f;

    for (int k0 = 0; k0 < DF; k0 += 8) {
        float4 av = make_float4(0.f, 0.f, 0.f, 0.f);
        if (arow) av = *(const float4*)(arow + k0 + akq);
        float4 bv = *(const float4*)(B + (size_t)(k0 + bk) * DM + n0 + bn);
        As[akq + 0][am] = av.x; As[akq + 1][am] = av.y;
        As[akq + 2][am] = av.z; As[akq + 3][am] = av.w;
        *(float4*)&Bs[bk][bn] = bv;
        __syncthreads();
        #pragma unroll
        for (int kk = 0; kk < 8; kk++) {
            float a[8], b[8];
            #pragma unroll
            for (int i = 0; i < 8; i++) a[i] = As[kk][ty * 8 + i];
            #pragma unroll
            for (int j = 0; j < 8; j++) b[j] = Bs[kk][tx * 8 + j];
            #pragma unroll
            for (int i = 0; i < 8; i++)
                #pragma unroll
                for (int j = 0; j < 8; j++)
                    acc[i][j] += a[i] * b[j];
        }
        __syncthreads();
    }

    // epilogue: + b2, scatter rows back to token positions
    const float* bb = b2 + (size_t)e * DM + n0 + tx * 8;
    float4 b2lo = *(const float4*)(bb);
    float4 b2hi = *(const float4*)(bb + 4);
    #pragma unroll
    for (int i = 0; i < 8; i++) {
        int m = m0 + ty * 8 + i;
        if (m < cnt) {
            int tok = g_list[off + m];
            float* orow = out + (size_t)tok * DM + n0 + tx * 8;
            float4 v0, v1;
            v0.x = acc[i][0] + b2lo.x;  v0.y = acc[i][1] + b2lo.y;
            v0.z = acc[i][2] + b2lo.z;  v0.w = acc[i][3] + b2lo.w;
            v1.x = acc[i][4] + b2hi.x;  v1.y = acc[i][5] + b2hi.y;
            v1.z = acc[i][6] + b2hi.z;  v1.w = acc[i][7] + b2hi.w;
            *(float4*)(orow)     = v0;
            *(float4*)(orow + 4) = v1;
        }
    }
}

// ---------------------------------------------------------------- launch ----
extern "C" void kernel_launch(void* const* d_in, const int* in_sizes, int n_in,
                              void* d_out, int out_size)
{
    const float* X   = (const float*)d_in[0];       // [4,4096,1024] fp32
    const int*   idx = (const int*)d_in[1];         // [4,4096] int32 (JAX x64 off)
    const float* W1  = (const float*)d_in[2];       // [8,1024,4096]
    const float* b1  = (const float*)d_in[3];       // [8,4096]
    const float* W2  = (const float*)d_in[4];       // [8,4096,1024]
    const float* b2  = (const float*)d_in[5];       // [8,1024]
    float*       out = (float*)d_out;               // [4,4096,1024]

    (void)in_sizes; (void)n_in; (void)out_size;

    k_route0<<<1, 32>>>();
    k_route1<<<(NTOK + 255) / 256, 256>>>(idx);
    k_route2<<<1, 32>>>();
    k_route3<<<(NTOK + 255) / 256, 256>>>(idx);

    k_gemm1<<<dim3(NTOK / 128, DF / 128, NE), 256>>>(X, W1, b1);
    k_gemm2<<<dim3(NTOK / 128, DM / 128, NE), 256>>>(W2, b2, out);
}